// round 1
// baseline (speedup 1.0000x reference)
#include <cuda_runtime.h>
#include <cuda_fp16.h>
#include <cstdint>

// Problem dims (fixed by setup_inputs)
#define N_ROWS 16384
#define D_DIM  768
#define P_DIM  2048
#define C_DIM  1000
#define C_PAD  1024

// Scratch (allocation-free: __device__ globals)
__device__ __half g_hn[(size_t)N_ROWS * D_DIM];   // normalized h, fp16
__device__ __half g_pn[(size_t)P_DIM  * D_DIM];   // normalized prototypes, fp16
__device__ __half g_act[(size_t)N_ROWS * P_DIM];  // activations, fp16
__device__ __half g_pct[(size_t)C_PAD  * P_DIM];  // prototype_class transposed+padded, fp16

// ---------------------------------------------------------------------------
// Row L2 normalize: one block per row, fp32 in -> fp16 out
// ---------------------------------------------------------------------------
__global__ void normalize_rows_kernel(const float* __restrict__ x,
                                      __half* __restrict__ y, int D) {
    int row = blockIdx.x;
    const float* xr = x + (size_t)row * D;
    float ss = 0.f;
    for (int i = threadIdx.x; i < D; i += blockDim.x) {
        float v = xr[i];
        ss += v * v;
    }
    #pragma unroll
    for (int o = 16; o; o >>= 1) ss += __shfl_xor_sync(0xffffffff, ss, o);
    __shared__ float wsum[8];
    int w = threadIdx.x >> 5, l = threadIdx.x & 31;
    if (l == 0) wsum[w] = ss;
    __syncthreads();
    if (w == 0) {
        float v = (l < (int)(blockDim.x >> 5)) ? wsum[l] : 0.f;
        #pragma unroll
        for (int o = 4; o; o >>= 1) v += __shfl_xor_sync(0xffffffff, v, o);
        if (l == 0) wsum[0] = v;
    }
    __syncthreads();
    float inv = 1.0f / fmaxf(sqrtf(wsum[0]), 1e-12f);
    __half* yr = y + (size_t)row * D;
    for (int i = threadIdx.x; i < D; i += blockDim.x)
        yr[i] = __float2half(xr[i] * inv);
}

// ---------------------------------------------------------------------------
// Transpose prototype_class [P, C] fp32 -> g_pct [C_PAD, P] fp16, zero-padded
// ---------------------------------------------------------------------------
__global__ void transpose_pc_kernel(const float* __restrict__ pc) {
    __shared__ float tile[32][33];
    int p0 = blockIdx.x * 32, c0 = blockIdx.y * 32;
    int tx = threadIdx.x, ty = threadIdx.y;   // block (32, 8)
    #pragma unroll
    for (int j = 0; j < 32; j += 8) {
        int p = p0 + ty + j, c = c0 + tx;
        tile[ty + j][tx] = (c < C_DIM) ? pc[(size_t)p * C_DIM + c] : 0.f;
    }
    __syncthreads();
    #pragma unroll
    for (int j = 0; j < 32; j += 8) {
        int c = c0 + ty + j, p = p0 + tx;
        g_pct[(size_t)c * P_DIM + p] = __float2half(tile[tx][ty + j]);
    }
}

// ---------------------------------------------------------------------------
// Tiled fp16 GEMM (TN): C[M,N] = A[M,K] * B[N,K]^T, fp32 accum.
// Block tile 128x128x32, 256 threads (8 warps, 2x4), warp tile 64x32.
// 3-stage cp.async pipeline; ldmatrix.x4 frag loads; mma.m16n8k16.
// smem rows padded to 40 halfs (80B) -> conflict-free ldmatrix phases.
// ---------------------------------------------------------------------------
#define PADK   40
#define STAGES 3
#define GEMM_SMEM_BYTES (STAGES * 2 * 128 * PADK * sizeof(__half))  // 61440

__device__ __forceinline__ uint32_t smem_u32(const void* p) {
    return (uint32_t)__cvta_generic_to_shared(p);
}

template<int KDIM, bool ACT_EPI>
__global__ void __launch_bounds__(256, 2) gemm128_kernel(
    const __half* __restrict__ A, const __half* __restrict__ B,
    __half* __restrict__ outH, float* __restrict__ outF,
    const float* __restrict__ tempPtr)
{
    extern __shared__ __half sm[];
    const int tid  = threadIdx.x;
    const int warp = tid >> 5, lane = tid & 31;
    const int wm = warp >> 2, wn = warp & 3;
    const int m0 = blockIdx.y * 128, n0 = blockIdx.x * 128;

    auto As = [&](int s) { return sm + (size_t)s * 2 * 128 * PADK; };
    auto Bs = [&](int s) { return sm + (size_t)s * 2 * 128 * PADK + 128 * PADK; };

    float acc[4][4][4];
    #pragma unroll
    for (int f = 0; f < 4; ++f)
        #pragma unroll
        for (int n = 0; n < 4; ++n)
            #pragma unroll
            for (int k = 0; k < 4; ++k) acc[f][n][k] = 0.f;

    const int KT = KDIM / 32;

    auto load_tile = [&](int kt, int s) {
        const __half* ga = A + (size_t)m0 * KDIM + kt * 32;
        const __half* gb = B + (size_t)n0 * KDIM + kt * 32;
        __half* sa = As(s); __half* sb = Bs(s);
        #pragma unroll
        for (int i = 0; i < 2; ++i) {
            int l = tid + i * 256;
            int row = l >> 2, ch = l & 3;
            uint32_t da = smem_u32(sa + row * PADK + ch * 8);
            const __half* srca = ga + (size_t)row * KDIM + ch * 8;
            asm volatile("cp.async.cg.shared.global [%0], [%1], 16;\n"
                         :: "r"(da), "l"(srca));
            uint32_t db = smem_u32(sb + row * PADK + ch * 8);
            const __half* srcb = gb + (size_t)row * KDIM + ch * 8;
            asm volatile("cp.async.cg.shared.global [%0], [%1], 16;\n"
                         :: "r"(db), "l"(srcb));
        }
    };

    // Prologue: stages 0..STAGES-2
    #pragma unroll
    for (int s = 0; s < STAGES - 1; ++s) {
        load_tile(s, s);
        asm volatile("cp.async.commit_group;\n");
    }

    for (int kt = 0; kt < KT; ++kt) {
        asm volatile("cp.async.wait_group %0;\n" :: "n"(STAGES - 2));
        __syncthreads();
        const int cur = kt % STAGES;
        const int nxt = kt + STAGES - 1;
        if (nxt < KT) load_tile(nxt, nxt % STAGES);
        asm volatile("cp.async.commit_group;\n");

        const __half* sa = As(cur);
        const __half* sb = Bs(cur);
        #pragma unroll
        for (int ks = 0; ks < 2; ++ks) {
            uint32_t a[4][4], b[2][4];
            #pragma unroll
            for (int f = 0; f < 4; ++f) {
                int row = wm * 64 + f * 16 + (lane & 15);
                int col = ks * 16 + (lane >> 4) * 8;
                uint32_t addr = smem_u32(sa + row * PADK + col);
                asm volatile(
                    "ldmatrix.sync.aligned.m8n8.x4.shared.b16 {%0,%1,%2,%3}, [%4];\n"
                    : "=r"(a[f][0]), "=r"(a[f][1]), "=r"(a[f][2]), "=r"(a[f][3])
                    : "r"(addr));
            }
            #pragma unroll
            for (int p = 0; p < 2; ++p) {
                int row = wn * 32 + p * 16 + (lane & 7) + ((lane >> 4) << 3);
                int col = ks * 16 + ((lane >> 3) & 1) * 8;
                uint32_t addr = smem_u32(sb + row * PADK + col);
                asm volatile(
                    "ldmatrix.sync.aligned.m8n8.x4.shared.b16 {%0,%1,%2,%3}, [%4];\n"
                    : "=r"(b[p][0]), "=r"(b[p][1]), "=r"(b[p][2]), "=r"(b[p][3])
                    : "r"(addr));
            }
            #pragma unroll
            for (int f = 0; f < 4; ++f)
                #pragma unroll
                for (int nf = 0; nf < 4; ++nf) {
                    uint32_t b0 = b[nf >> 1][(nf & 1) * 2 + 0];
                    uint32_t b1 = b[nf >> 1][(nf & 1) * 2 + 1];
                    float* c = acc[f][nf];
                    asm volatile(
                        "mma.sync.aligned.m16n8k16.row.col.f32.f16.f16.f32 "
                        "{%0,%1,%2,%3},{%4,%5,%6,%7},{%8,%9},{%0,%1,%2,%3};\n"
                        : "+f"(c[0]), "+f"(c[1]), "+f"(c[2]), "+f"(c[3])
                        : "r"(a[f][0]), "r"(a[f][1]), "r"(a[f][2]), "r"(a[f][3]),
                          "r"(b0), "r"(b1));
                }
        }
    }

    // Epilogue
    if (ACT_EPI) {
        float t = __ldg(tempPtr);
        float tau = (t > 20.f) ? t : log1pf(expf(t));   // softplus
        #pragma unroll
        for (int f = 0; f < 4; ++f)
            #pragma unroll
            for (int nf = 0; nf < 4; ++nf) {
                int row = m0 + wm * 64 + f * 16 + (lane >> 2);
                int col = n0 + wn * 32 + nf * 8 + (lane & 3) * 2;
                #pragma unroll
                for (int h = 0; h < 2; ++h) {
                    int r = row + h * 8;
                    float d0 = acc[f][nf][h * 2 + 0];
                    float d1 = acc[f][nf][h * 2 + 1];
                    // h_sq = p_sq = 1 after normalization
                    float a0 = __expf(-tau * sqrtf(fmaxf(2.f - 2.f * d0, 0.f)));
                    float a1 = __expf(-tau * sqrtf(fmaxf(2.f - 2.f * d1, 0.f)));
                    __half2 hv = __floats2half2_rn(a0, a1);
                    *(__half2*)(outH + (size_t)r * P_DIM + col) = hv;
                }
            }
    } else {
        #pragma unroll
        for (int f = 0; f < 4; ++f)
            #pragma unroll
            for (int nf = 0; nf < 4; ++nf) {
                int row = m0 + wm * 64 + f * 16 + (lane >> 2);
                int col = n0 + wn * 32 + nf * 8 + (lane & 3) * 2;
                #pragma unroll
                for (int h = 0; h < 2; ++h) {
                    int r = row + h * 8;
                    if (col < C_DIM)
                        outF[(size_t)r * C_DIM + col] = acc[f][nf][h * 2 + 0];
                    if (col + 1 < C_DIM)
                        outF[(size_t)r * C_DIM + col + 1] = acc[f][nf][h * 2 + 1];
                }
            }
    }
}

// ---------------------------------------------------------------------------
// kernel_launch: 5 launches, all graph-capturable, no allocations.
// Inputs: h [N,D] f32, prototypes [P,D] f32, prototype_class [P,C] f32,
//         temperature [1] f32. Output: class_logits [N,C] f32.
// ---------------------------------------------------------------------------
extern "C" void kernel_launch(void* const* d_in, const int* in_sizes, int n_in,
                              void* d_out, int out_size) {
    const float* h    = (const float*)d_in[0];
    const float* prot = (const float*)d_in[1];
    const float* pc   = (const float*)d_in[2];
    const float* temp = (const float*)d_in[3];
    float* out = (float*)d_out;

    __half *hn = nullptr, *pn = nullptr, *act = nullptr;
    cudaGetSymbolAddress((void**)&hn,  g_hn);
    cudaGetSymbolAddress((void**)&pn,  g_pn);
    cudaGetSymbolAddress((void**)&act, g_act);
    __half* pct = nullptr;
    cudaGetSymbolAddress((void**)&pct, g_pct);

    cudaFuncSetAttribute(gemm128_kernel<D_DIM, true>,
                         cudaFuncAttributeMaxDynamicSharedMemorySize,
                         (int)GEMM_SMEM_BYTES);
    cudaFuncSetAttribute(gemm128_kernel<P_DIM, false>,
                         cudaFuncAttributeMaxDynamicSharedMemorySize,
                         (int)GEMM_SMEM_BYTES);

    // 1) normalize h -> fp16
    normalize_rows_kernel<<<N_ROWS, 256>>>(h, hn, D_DIM);
    // 2) normalize prototypes -> fp16
    normalize_rows_kernel<<<P_DIM, 256>>>(prot, pn, D_DIM);
    // 3) transpose + pad prototype_class -> fp16 [C_PAD, P]
    transpose_pc_kernel<<<dim3(P_DIM / 32, C_PAD / 32), dim3(32, 8)>>>(pc);
    // 4) GEMM1 + dist/exp epilogue -> activations fp16 [N, P]
    gemm128_kernel<D_DIM, true>
        <<<dim3(P_DIM / 128, N_ROWS / 128), 256, GEMM_SMEM_BYTES>>>(
            hn, pn, act, nullptr, temp);
    // 5) GEMM2 -> logits fp32 [N, C]
    gemm128_kernel<P_DIM, false>
        <<<dim3(C_PAD / 128, N_ROWS / 128), 256, GEMM_SMEM_BYTES>>>(
            act, pct, nullptr, out, nullptr);
}

// round 3
// speedup vs baseline: 1.0757x; 1.0757x over previous
#include <cuda_runtime.h>
#include <cuda_fp16.h>
#include <cstdint>

// Problem dims (fixed by setup_inputs)
#define N_ROWS 16384
#define D_DIM  768
#define P_DIM  2048
#define C_DIM  1000
#define C_PAD  1024

// Scratch (allocation-free: __device__ globals)
__device__ __half g_hn[(size_t)N_ROWS * D_DIM];   // normalized h, fp16
__device__ __half g_pn[(size_t)P_DIM  * D_DIM];   // normalized prototypes, fp16
__device__ __half g_act[(size_t)N_ROWS * P_DIM];  // activations, fp16
__device__ __half g_pct[(size_t)C_PAD  * P_DIM];  // prototype_class transposed+padded

// ---------------------------------------------------------------------------
// Row L2 normalize: one block per row, fp32 in -> fp16 out
// ---------------------------------------------------------------------------
__global__ void normalize_rows_kernel(const float* __restrict__ x,
                                      __half* __restrict__ y, int D) {
    int row = blockIdx.x;
    const float* xr = x + (size_t)row * D;
    float ss = 0.f;
    for (int i = threadIdx.x; i < D; i += blockDim.x) {
        float v = xr[i];
        ss += v * v;
    }
    #pragma unroll
    for (int o = 16; o; o >>= 1) ss += __shfl_xor_sync(0xffffffff, ss, o);
    __shared__ float wsum[8];
    int w = threadIdx.x >> 5, l = threadIdx.x & 31;
    if (l == 0) wsum[w] = ss;
    __syncthreads();
    if (w == 0) {
        float v = (l < (int)(blockDim.x >> 5)) ? wsum[l] : 0.f;
        #pragma unroll
        for (int o = 4; o; o >>= 1) v += __shfl_xor_sync(0xffffffff, v, o);
        if (l == 0) wsum[0] = v;
    }
    __syncthreads();
    float inv = 1.0f / fmaxf(sqrtf(wsum[0]), 1e-12f);
    __half* yr = y + (size_t)row * D;
    for (int i = threadIdx.x; i < D; i += blockDim.x)
        yr[i] = __float2half(xr[i] * inv);
}

// ---------------------------------------------------------------------------
// Transpose prototype_class [P, C] fp32 -> g_pct [C_PAD, P] fp16, zero-padded
// ---------------------------------------------------------------------------
__global__ void transpose_pc_kernel(const float* __restrict__ pc) {
    __shared__ float tile[32][33];
    int p0 = blockIdx.x * 32, c0 = blockIdx.y * 32;
    int tx = threadIdx.x, ty = threadIdx.y;   // block (32, 8)
    #pragma unroll
    for (int j = 0; j < 32; j += 8) {
        int p = p0 + ty + j, c = c0 + tx;
        tile[ty + j][tx] = (c < C_DIM) ? pc[(size_t)p * C_DIM + c] : 0.f;
    }
    __syncthreads();
    #pragma unroll
    for (int j = 0; j < 32; j += 8) {
        int c = c0 + ty + j, p = p0 + tx;
        g_pct[(size_t)c * P_DIM + p] = __float2half(tile[tx][ty + j]);
    }
}

// ---------------------------------------------------------------------------
// Tiled fp16 GEMM (TN): C[M,N] = A[M,K] * B[N,K]^T, fp32 accum.
// CTA tile 128x128x32, 128 threads (4 warps, 2x2), warp tile 64x64.
// 4-stage cp.async pipeline; ldmatrix.x4; mma.m16n8k16; 2 CTAs/SM.
// smem row stride 40 halfs (80B) -> conflict-free ldmatrix phases.
// ---------------------------------------------------------------------------
#define PADK   40
#define STAGES 4
#define GEMM_SMEM_BYTES (STAGES * 2 * 128 * PADK * sizeof(__half))  // 81920

__device__ __forceinline__ uint32_t smem_u32(const void* p) {
    return (uint32_t)__cvta_generic_to_shared(p);
}

template<int KDIM, bool ACT_EPI>
__global__ void __launch_bounds__(128, 2) gemm128_kernel(
    const __half* __restrict__ A, const __half* __restrict__ B,
    __half* __restrict__ outH, float* __restrict__ outF,
    const float* __restrict__ tempPtr)
{
    extern __shared__ __half sm[];
    const int tid  = threadIdx.x;
    const int warp = tid >> 5, lane = tid & 31;
    const int wm = warp >> 1, wn = warp & 1;
    const int m0 = blockIdx.y * 128, n0 = blockIdx.x * 128;

    auto As = [&](int s) { return sm + (size_t)s * 2 * 128 * PADK; };
    auto Bs = [&](int s) { return sm + (size_t)s * 2 * 128 * PADK + 128 * PADK; };

    float acc[4][8][4];
    #pragma unroll
    for (int f = 0; f < 4; ++f)
        #pragma unroll
        for (int n = 0; n < 8; ++n)
            #pragma unroll
            for (int k = 0; k < 4; ++k) acc[f][n][k] = 0.f;

    const int KT = KDIM / 32;

    auto load_tile = [&](int kt, int s) {
        const __half* ga = A + (size_t)m0 * KDIM + kt * 32;
        const __half* gb = B + (size_t)n0 * KDIM + kt * 32;
        __half* sa = As(s); __half* sb = Bs(s);
        // 128 rows x 32 halfs each of A and B; 16B per cp.async.
        // 512 chunks per matrix / 128 threads = 4 each.
        #pragma unroll
        for (int i = 0; i < 4; ++i) {
            int l = tid + i * 128;
            int row = l >> 2, ch = l & 3;
            uint32_t da = smem_u32(sa + row * PADK + ch * 8);
            const __half* srca = ga + (size_t)row * KDIM + ch * 8;
            asm volatile("cp.async.cg.shared.global [%0], [%1], 16;\n"
                         :: "r"(da), "l"(srca));
            uint32_t db = smem_u32(sb + row * PADK + ch * 8);
            const __half* srcb = gb + (size_t)row * KDIM + ch * 8;
            asm volatile("cp.async.cg.shared.global [%0], [%1], 16;\n"
                         :: "r"(db), "l"(srcb));
        }
    };

    // Prologue
    #pragma unroll
    for (int s = 0; s < STAGES - 1; ++s) {
        load_tile(s, s);
        asm volatile("cp.async.commit_group;\n");
    }

    for (int kt = 0; kt < KT; ++kt) {
        asm volatile("cp.async.wait_group %0;\n" :: "n"(STAGES - 2));
        __syncthreads();
        const int cur = kt % STAGES;
        const int nxt = kt + STAGES - 1;
        if (nxt < KT) load_tile(nxt, nxt % STAGES);
        asm volatile("cp.async.commit_group;\n");

        const __half* sa = As(cur);
        const __half* sb = Bs(cur);
        #pragma unroll
        for (int ks = 0; ks < 2; ++ks) {
            uint32_t a[4][4], b[4][4];
            #pragma unroll
            for (int f = 0; f < 4; ++f) {
                int row = wm * 64 + f * 16 + (lane & 15);
                int col = ks * 16 + (lane >> 4) * 8;
                uint32_t addr = smem_u32(sa + row * PADK + col);
                asm volatile(
                    "ldmatrix.sync.aligned.m8n8.x4.shared.b16 {%0,%1,%2,%3}, [%4];\n"
                    : "=r"(a[f][0]), "=r"(a[f][1]), "=r"(a[f][2]), "=r"(a[f][3])
                    : "r"(addr));
            }
            #pragma unroll
            for (int p = 0; p < 4; ++p) {
                int row = wn * 64 + p * 16 + (lane & 7) + ((lane >> 4) << 3);
                int col = ks * 16 + ((lane >> 3) & 1) * 8;
                uint32_t addr = smem_u32(sb + row * PADK + col);
                asm volatile(
                    "ldmatrix.sync.aligned.m8n8.x4.shared.b16 {%0,%1,%2,%3}, [%4];\n"
                    : "=r"(b[p][0]), "=r"(b[p][1]), "=r"(b[p][2]), "=r"(b[p][3])
                    : "r"(addr));
            }
            #pragma unroll
            for (int f = 0; f < 4; ++f)
                #pragma unroll
                for (int nf = 0; nf < 8; ++nf) {
                    uint32_t b0 = b[nf >> 1][(nf & 1) * 2 + 0];
                    uint32_t b1 = b[nf >> 1][(nf & 1) * 2 + 1];
                    float* c = acc[f][nf];
                    asm volatile(
                        "mma.sync.aligned.m16n8k16.row.col.f32.f16.f16.f32 "
                        "{%0,%1,%2,%3},{%4,%5,%6,%7},{%8,%9},{%0,%1,%2,%3};\n"
                        : "+f"(c[0]), "+f"(c[1]), "+f"(c[2]), "+f"(c[3])
                        : "r"(a[f][0]), "r"(a[f][1]), "r"(a[f][2]), "r"(a[f][3]),
                          "r"(b0), "r"(b1));
                }
        }
    }

    // Epilogue
    if (ACT_EPI) {
        float t = __ldg(tempPtr);
        float tau = (t > 20.f) ? t : log1pf(expf(t));   // softplus
        #pragma unroll
        for (int f = 0; f < 4; ++f)
            #pragma unroll
            for (int nf = 0; nf < 8; ++nf) {
                int row = m0 + wm * 64 + f * 16 + (lane >> 2);
                int col = n0 + wn * 64 + nf * 8 + (lane & 3) * 2;
                #pragma unroll
                for (int hh = 0; hh < 2; ++hh) {
                    int r = row + hh * 8;
                    float d0 = acc[f][nf][hh * 2 + 0];
                    float d1 = acc[f][nf][hh * 2 + 1];
                    // h_sq = p_sq = 1 after normalization
                    float a0 = __expf(-tau * sqrtf(fmaxf(2.f - 2.f * d0, 0.f)));
                    float a1 = __expf(-tau * sqrtf(fmaxf(2.f - 2.f * d1, 0.f)));
                    *(__half2*)(outH + (size_t)r * P_DIM + col) =
                        __floats2half2_rn(a0, a1);
                }
            }
    } else {
        #pragma unroll
        for (int f = 0; f < 4; ++f)
            #pragma unroll
            for (int nf = 0; nf < 8; ++nf) {
                int row = m0 + wm * 64 + f * 16 + (lane >> 2);
                int col = n0 + wn * 64 + nf * 8 + (lane & 3) * 2;
                if (col < C_DIM) {   // C_DIM even -> pair never straddles
                    #pragma unroll
                    for (int hh = 0; hh < 2; ++hh) {
                        int r = row + hh * 8;
                        float2 v = make_float2(acc[f][nf][hh * 2 + 0],
                                               acc[f][nf][hh * 2 + 1]);
                        *(float2*)(outF + (size_t)r * C_DIM + col) = v;
                    }
                }
            }
    }
}

// ---------------------------------------------------------------------------
// kernel_launch: 5 launches, all graph-capturable, no allocations.
// ---------------------------------------------------------------------------
extern "C" void kernel_launch(void* const* d_in, const int* in_sizes, int n_in,
                              void* d_out, int out_size) {
    const float* h    = (const float*)d_in[0];
    const float* prot = (const float*)d_in[1];
    const float* pc   = (const float*)d_in[2];
    const float* temp = (const float*)d_in[3];
    float* out = (float*)d_out;

    __half *hn = nullptr, *pn = nullptr, *act = nullptr, *pct = nullptr;
    cudaGetSymbolAddress((void**)&hn,  g_hn);
    cudaGetSymbolAddress((void**)&pn,  g_pn);
    cudaGetSymbolAddress((void**)&act, g_act);
    cudaGetSymbolAddress((void**)&pct, g_pct);

    cudaFuncSetAttribute(gemm128_kernel<D_DIM, true>,
                         cudaFuncAttributeMaxDynamicSharedMemorySize,
                         (int)GEMM_SMEM_BYTES);
    cudaFuncSetAttribute(gemm128_kernel<P_DIM, false>,
                         cudaFuncAttributeMaxDynamicSharedMemorySize,
                         (int)GEMM_SMEM_BYTES);

    // 1) normalize h -> fp16
    normalize_rows_kernel<<<N_ROWS, 256>>>(h, hn, D_DIM);
    // 2) normalize prototypes -> fp16
    normalize_rows_kernel<<<P_DIM, 256>>>(prot, pn, D_DIM);
    // 3) transpose + pad prototype_class -> fp16 [C_PAD, P]
    transpose_pc_kernel<<<dim3(P_DIM / 32, C_PAD / 32), dim3(32, 8)>>>(pc);
    // 4) GEMM1 + dist/exp epilogue -> activations fp16 [N, P]
    gemm128_kernel<D_DIM, true>
        <<<dim3(P_DIM / 128, N_ROWS / 128), 128, GEMM_SMEM_BYTES>>>(
            hn, pn, act, nullptr, temp);
    // 5) GEMM2 -> logits fp32 [N, C]
    gemm128_kernel<P_DIM, false>
        <<<dim3(C_PAD / 128, N_ROWS / 128), 128, GEMM_SMEM_BYTES>>>(
            act, pct, nullptr, out, nullptr);
}

// round 4
// speedup vs baseline: 1.0814x; 1.0052x over previous
#include <cuda_runtime.h>
#include <cuda_fp16.h>
#include <cstdint>

// Problem dims (fixed by setup_inputs)
#define N_ROWS 16384
#define D_DIM  768
#define P_DIM  2048
#define C_DIM  1000
#define C_PAD  1024

// Scratch (allocation-free: __device__ globals)
__device__ __half g_hn[(size_t)N_ROWS * D_DIM];   // normalized h, fp16
__device__ __half g_pn[(size_t)P_DIM  * D_DIM];   // normalized prototypes, fp16
__device__ __half g_act[(size_t)N_ROWS * P_DIM];  // activations, fp16
__device__ __half g_pct[(size_t)C_PAD  * P_DIM];  // prototype_class transposed+padded

// ---------------------------------------------------------------------------
// Row L2 normalize: one block per row, fp32 in -> fp16 out
// ---------------------------------------------------------------------------
__global__ void normalize_rows_kernel(const float* __restrict__ x,
                                      __half* __restrict__ y, int D) {
    int row = blockIdx.x;
    const float* xr = x + (size_t)row * D;
    float ss = 0.f;
    for (int i = threadIdx.x; i < D; i += blockDim.x) {
        float v = xr[i];
        ss += v * v;
    }
    #pragma unroll
    for (int o = 16; o; o >>= 1) ss += __shfl_xor_sync(0xffffffff, ss, o);
    __shared__ float wsum[8];
    int w = threadIdx.x >> 5, l = threadIdx.x & 31;
    if (l == 0) wsum[w] = ss;
    __syncthreads();
    if (w == 0) {
        float v = (l < (int)(blockDim.x >> 5)) ? wsum[l] : 0.f;
        #pragma unroll
        for (int o = 4; o; o >>= 1) v += __shfl_xor_sync(0xffffffff, v, o);
        if (l == 0) wsum[0] = v;
    }
    __syncthreads();
    float inv = 1.0f / fmaxf(sqrtf(wsum[0]), 1e-12f);
    __half* yr = y + (size_t)row * D;
    for (int i = threadIdx.x; i < D; i += blockDim.x)
        yr[i] = __float2half(xr[i] * inv);
}

// ---------------------------------------------------------------------------
// Transpose prototype_class [P, C] fp32 -> g_pct [C_PAD, P] fp16, zero-padded
// ---------------------------------------------------------------------------
__global__ void transpose_pc_kernel(const float* __restrict__ pc) {
    __shared__ float tile[32][33];
    int p0 = blockIdx.x * 32, c0 = blockIdx.y * 32;
    int tx = threadIdx.x, ty = threadIdx.y;   // block (32, 8)
    #pragma unroll
    for (int j = 0; j < 32; j += 8) {
        int p = p0 + ty + j, c = c0 + tx;
        tile[ty + j][tx] = (c < C_DIM) ? pc[(size_t)p * C_DIM + c] : 0.f;
    }
    __syncthreads();
    #pragma unroll
    for (int j = 0; j < 32; j += 8) {
        int c = c0 + ty + j, p = p0 + tx;
        g_pct[(size_t)c * P_DIM + p] = __float2half(tile[tx][ty + j]);
    }
}

// ---------------------------------------------------------------------------
// Tiled fp16 GEMM (TN): C[M,N] = A[M,K] * B[N,K]^T, fp32 accum.
// CTA tile 128x128x32, 128 threads (4 warps, 2x2), warp tile 64x64.
// 4-stage cp.async pipeline; register double-buffered fragments with
// hand-interleaved LDSM/HMMA schedule; mma.m16n8k16; 2 CTAs/SM.
// ---------------------------------------------------------------------------
#define PADK   40
#define STAGES 4
#define GEMM_SMEM_BYTES (STAGES * 2 * 128 * PADK * sizeof(__half))  // 81920

__device__ __forceinline__ uint32_t smem_u32(const void* p) {
    return (uint32_t)__cvta_generic_to_shared(p);
}

template<int KDIM, bool ACT_EPI>
__global__ void __launch_bounds__(128, 2) gemm128_kernel(
    const __half* __restrict__ A, const __half* __restrict__ B,
    __half* __restrict__ outH, float* __restrict__ outF,
    const float* __restrict__ tempPtr)
{
    extern __shared__ __half sm[];
    const int tid  = threadIdx.x;
    const int warp = tid >> 5, lane = tid & 31;
    const int wm = warp >> 1, wn = warp & 1;
    const int m0 = blockIdx.y * 128, n0 = blockIdx.x * 128;

    auto As = [&](int s) { return sm + (size_t)s * 2 * 128 * PADK; };
    auto Bs = [&](int s) { return sm + (size_t)s * 2 * 128 * PADK + 128 * PADK; };

    float acc[4][8][4];
    #pragma unroll
    for (int f = 0; f < 4; ++f)
        #pragma unroll
        for (int n = 0; n < 8; ++n)
            #pragma unroll
            for (int k = 0; k < 4; ++k) acc[f][n][k] = 0.f;

    const int KT = KDIM / 32;

    auto load_tile = [&](int kt, int s) {
        const __half* ga = A + (size_t)m0 * KDIM + kt * 32;
        const __half* gb = B + (size_t)n0 * KDIM + kt * 32;
        __half* sa = As(s); __half* sb = Bs(s);
        #pragma unroll
        for (int i = 0; i < 4; ++i) {
            int l = tid + i * 128;
            int row = l >> 2, ch = l & 3;
            uint32_t da = smem_u32(sa + row * PADK + ch * 8);
            const __half* srca = ga + (size_t)row * KDIM + ch * 8;
            asm volatile("cp.async.cg.shared.global [%0], [%1], 16;\n"
                         :: "r"(da), "l"(srca));
            uint32_t db = smem_u32(sb + row * PADK + ch * 8);
            const __half* srcb = gb + (size_t)row * KDIM + ch * 8;
            asm volatile("cp.async.cg.shared.global [%0], [%1], 16;\n"
                         :: "r"(db), "l"(srcb));
        }
    };

    // Fragment load / mma primitives
    auto lda = [&](uint32_t* r, const __half* sa, int f, int ks) {
        int row = wm * 64 + f * 16 + (lane & 15);
        int col = ks * 16 + (lane >> 4) * 8;
        uint32_t addr = smem_u32(sa + row * PADK + col);
        asm volatile(
            "ldmatrix.sync.aligned.m8n8.x4.shared.b16 {%0,%1,%2,%3}, [%4];\n"
            : "=r"(r[0]), "=r"(r[1]), "=r"(r[2]), "=r"(r[3]) : "r"(addr));
    };
    auto ldb = [&](uint32_t* r, const __half* sb, int p, int ks) {
        int row = wn * 64 + p * 16 + (lane & 7) + ((lane >> 4) << 3);
        int col = ks * 16 + ((lane >> 3) & 1) * 8;
        uint32_t addr = smem_u32(sb + row * PADK + col);
        asm volatile(
            "ldmatrix.sync.aligned.m8n8.x4.shared.b16 {%0,%1,%2,%3}, [%4];\n"
            : "=r"(r[0]), "=r"(r[1]), "=r"(r[2]), "=r"(r[3]) : "r"(addr));
    };
    auto hmma = [&](float* c, const uint32_t* a4, uint32_t b0, uint32_t b1) {
        asm volatile(
            "mma.sync.aligned.m16n8k16.row.col.f32.f16.f16.f32 "
            "{%0,%1,%2,%3},{%4,%5,%6,%7},{%8,%9},{%0,%1,%2,%3};\n"
            : "+f"(c[0]), "+f"(c[1]), "+f"(c[2]), "+f"(c[3])
            : "r"(a4[0]), "r"(a4[1]), "r"(a4[2]), "r"(a4[3]), "r"(b0), "r"(b1));
    };

    uint32_t a[2][4][4], b[2][4][4];   // double-buffered fragments (ks parity)

    // Prologue
    #pragma unroll
    for (int s = 0; s < STAGES - 1; ++s) {
        load_tile(s, s);
        asm volatile("cp.async.commit_group;\n");
    }

    for (int kt = 0; kt < KT; ++kt) {
        asm volatile("cp.async.wait_group %0;\n" :: "n"(STAGES - 2));
        __syncthreads();
        const int cur = kt % STAGES;
        const int nxt = kt + STAGES - 1;
        if (nxt < KT) load_tile(nxt, nxt % STAGES);
        asm volatile("cp.async.commit_group;\n");

        const __half* sa = As(cur);
        const __half* sb = Bs(cur);

        // --- phase 0: fragments for ks=0 (A + first half of B) ---
        lda(a[0][0], sa, 0, 0); lda(a[0][1], sa, 1, 0);
        lda(a[0][2], sa, 2, 0); lda(a[0][3], sa, 3, 0);
        ldb(b[0][0], sb, 0, 0); ldb(b[0][1], sb, 1, 0);

        // --- phase 1: HMMA ks0 nf0..3; interleave 8 LDSM (b0 tail, a1, b1 head)
        #pragma unroll
        for (int nf = 0; nf < 4; ++nf)
            #pragma unroll
            for (int f = 0; f < 4; ++f) {
                hmma(acc[f][nf], a[0][f],
                     b[0][nf >> 1][(nf & 1) * 2], b[0][nf >> 1][(nf & 1) * 2 + 1]);
                const int i = nf * 4 + f;
                if ((i & 1) == 1) {
                    const int q = i >> 1;   // 0..7
                    if      (q == 0) ldb(b[0][2], sb, 2, 0);
                    else if (q == 1) ldb(b[0][3], sb, 3, 0);
                    else if (q == 2) lda(a[1][0], sa, 0, 1);
                    else if (q == 3) lda(a[1][1], sa, 1, 1);
                    else if (q == 4) lda(a[1][2], sa, 2, 1);
                    else if (q == 5) lda(a[1][3], sa, 3, 1);
                    else if (q == 6) ldb(b[1][0], sb, 0, 1);
                    else             ldb(b[1][1], sb, 1, 1);
                }
            }

        // --- phase 2: HMMA ks0 nf4..7; interleave b1 tail LDSM
        #pragma unroll
        for (int nf = 4; nf < 8; ++nf)
            #pragma unroll
            for (int f = 0; f < 4; ++f) {
                hmma(acc[f][nf], a[0][f],
                     b[0][nf >> 1][(nf & 1) * 2], b[0][nf >> 1][(nf & 1) * 2 + 1]);
                const int i = (nf - 4) * 4 + f;
                if (i == 1) ldb(b[1][2], sb, 2, 1);
                if (i == 3) ldb(b[1][3], sb, 3, 1);
            }

        // --- phase 3: HMMA ks1 (all fragments already resident)
        #pragma unroll
        for (int nf = 0; nf < 8; ++nf)
            #pragma unroll
            for (int f = 0; f < 4; ++f)
                hmma(acc[f][nf], a[1][f],
                     b[1][nf >> 1][(nf & 1) * 2], b[1][nf >> 1][(nf & 1) * 2 + 1]);
    }

    // Epilogue
    if (ACT_EPI) {
        float t = __ldg(tempPtr);
        float tau = (t > 20.f) ? t : log1pf(expf(t));   // softplus
        #pragma unroll
        for (int f = 0; f < 4; ++f)
            #pragma unroll
            for (int nf = 0; nf < 8; ++nf) {
                int row = m0 + wm * 64 + f * 16 + (lane >> 2);
                int col = n0 + wn * 64 + nf * 8 + (lane & 3) * 2;
                #pragma unroll
                for (int hh = 0; hh < 2; ++hh) {
                    int r = row + hh * 8;
                    float d0 = acc[f][nf][hh * 2 + 0];
                    float d1 = acc[f][nf][hh * 2 + 1];
                    // h_sq = p_sq = 1 after normalization
                    float a0 = __expf(-tau * sqrtf(fmaxf(2.f - 2.f * d0, 0.f)));
                    float a1 = __expf(-tau * sqrtf(fmaxf(2.f - 2.f * d1, 0.f)));
                    *(__half2*)(outH + (size_t)r * P_DIM + col) =
                        __floats2half2_rn(a0, a1);
                }
            }
    } else {
        #pragma unroll
        for (int f = 0; f < 4; ++f)
            #pragma unroll
            for (int nf = 0; nf < 8; ++nf) {
                int row = m0 + wm * 64 + f * 16 + (lane >> 2);
                int col = n0 + wn * 64 + nf * 8 + (lane & 3) * 2;
                if (col < C_DIM) {   // C_DIM even -> pair never straddles
                    #pragma unroll
                    for (int hh = 0; hh < 2; ++hh) {
                        int r = row + hh * 8;
                        float2 v = make_float2(acc[f][nf][hh * 2 + 0],
                                               acc[f][nf][hh * 2 + 1]);
                        *(float2*)(outF + (size_t)r * C_DIM + col) = v;
                    }
                }
            }
    }
}

// ---------------------------------------------------------------------------
// kernel_launch: 5 launches, all graph-capturable, no allocations.
// ---------------------------------------------------------------------------
extern "C" void kernel_launch(void* const* d_in, const int* in_sizes, int n_in,
                              void* d_out, int out_size) {
    const float* h    = (const float*)d_in[0];
    const float* prot = (const float*)d_in[1];
    const float* pc   = (const float*)d_in[2];
    const float* temp = (const float*)d_in[3];
    float* out = (float*)d_out;

    __half *hn = nullptr, *pn = nullptr, *act = nullptr, *pct = nullptr;
    cudaGetSymbolAddress((void**)&hn,  g_hn);
    cudaGetSymbolAddress((void**)&pn,  g_pn);
    cudaGetSymbolAddress((void**)&act, g_act);
    cudaGetSymbolAddress((void**)&pct, g_pct);

    cudaFuncSetAttribute(gemm128_kernel<D_DIM, true>,
                         cudaFuncAttributeMaxDynamicSharedMemorySize,
                         (int)GEMM_SMEM_BYTES);
    cudaFuncSetAttribute(gemm128_kernel<P_DIM, false>,
                         cudaFuncAttributeMaxDynamicSharedMemorySize,
                         (int)GEMM_SMEM_BYTES);

    // 1) normalize h -> fp16
    normalize_rows_kernel<<<N_ROWS, 256>>>(h, hn, D_DIM);
    // 2) normalize prototypes -> fp16
    normalize_rows_kernel<<<P_DIM, 256>>>(prot, pn, D_DIM);
    // 3) transpose + pad prototype_class -> fp16 [C_PAD, P]
    transpose_pc_kernel<<<dim3(P_DIM / 32, C_PAD / 32), dim3(32, 8)>>>(pc);
    // 4) GEMM1 + dist/exp epilogue -> activations fp16 [N, P]
    gemm128_kernel<D_DIM, true>
        <<<dim3(P_DIM / 128, N_ROWS / 128), 128, GEMM_SMEM_BYTES>>>(
            hn, pn, act, nullptr, temp);
    // 5) GEMM2 -> logits fp32 [N, C]
    gemm128_kernel<P_DIM, false>
        <<<dim3(C_PAD / 128, N_ROWS / 128), 128, GEMM_SMEM_BYTES>>>(
            act, pct, nullptr, out, nullptr);
}